// round 16
// baseline (speedup 1.0000x reference)
#include <cuda_runtime.h>
#include <cuda_fp16.h>
#include <cuda_fp8.h>
#include <cstdint>

#define MAXN 20000
#define MAXE 320000
#define FIN  128
#define HID  64
#define MAXB 8

// ---------------- static device scratch (allocation-free rule) ----------------
// Invariant: g_cnt, g_partial, g_done are ZERO at kernel_launch entry.
__device__ __align__(16) __half g_hw[(size_t)MAXN * MAXB * HID];        // layer-1 feats, fp16, node-major
__device__ __align__(16) __half g_h1[(size_t)MAXN * MAXB * HID];        // layer-1 activations, fp16
__device__ __align__(16) unsigned char g_f8[(size_t)MAXN * MAXB * HID]; // layer-2 feats, fp8
__device__ __half g_w1t[FIN * HID];                                      // W1^T fp16 [n][k]
__device__ __half g_w2t[HID * HID];                                      // W2^T fp16 [n][k]
__device__ int    g_cnt[MAXN];
__device__ int    g_offs[MAXN + 1];
__device__ int    g_cursor[MAXN];
__device__ float  g_dis[MAXN];
__device__ int    g_csr_src[MAXE];
__device__ float  g_partial[MAXB * 64];
__device__ unsigned int g_done;

// ---------------- fp8 helpers ----------------
__device__ __forceinline__ float4 f8x4_to_f4(uint32_t p) {
    __half2_raw lo = __nv_cvt_fp8x2_to_halfraw2((__nv_fp8x2_storage_t)(p & 0xffffu), __NV_E4M3);
    __half2_raw hi = __nv_cvt_fp8x2_to_halfraw2((__nv_fp8x2_storage_t)(p >> 16), __NV_E4M3);
    float2 a = __half22float2(*(__half2*)&lo);
    float2 b = __half22float2(*(__half2*)&hi);
    return make_float4(a.x, a.y, b.x, b.y);
}
__device__ __forceinline__ unsigned short f2_to_f8x2(float a, float b) {
    return (unsigned short)__nv_cvt_float2_to_fp8x2(make_float2(a, b), __NV_SATFINITE, __NV_E4M3);
}

// ---------------- HMMA m16n8k16 fp16 -> fp32 ----------------
__device__ __forceinline__ void mma16816(float* c, uint32_t a0, uint32_t a1,
                                         uint32_t a2, uint32_t a3,
                                         uint32_t b0, uint32_t b1) {
    asm volatile(
        "mma.sync.aligned.m16n8k16.row.col.f32.f16.f16.f32 "
        "{%0,%1,%2,%3}, {%4,%5,%6,%7}, {%8,%9}, {%0,%1,%2,%3};"
        : "+f"(c[0]), "+f"(c[1]), "+f"(c[2]), "+f"(c[3])
        : "r"(a0), "r"(a1), "r"(a2), "r"(a3), "r"(b0), "r"(b1));
}

// ---------------- weight convert + transpose (once; separate kernel on purpose:
// in-GEMM transpose causes 16-way STS conflicts with the MMA-friendly stride) ----
__global__ void k_wconv(const float* __restrict__ W1, const float* __restrict__ W2) {
    int i = blockIdx.x * blockDim.x + threadIdx.x;
    if (i < FIN * HID) {
        int k = i >> 6, n = i & 63;
        g_w1t[n * FIN + k] = __float2half_rn(W1[i]);
    } else if (i < FIN * HID + HID * HID) {
        int j = i - FIN * HID;
        int k = j >> 6, n = j & 63;
        g_w2t[n * HID + k] = __float2half_rn(W2[j]);
    }
}

// ---------------- in-degree count (g_cnt zero on entry by invariant) ----------------
__global__ void k_count(const int* __restrict__ ei, int E) {
    int t = blockIdx.x * blockDim.x + threadIdx.x;
    int e = t * 4;
    if ((E & 3) == 0) {
        if (e < E) {
            int4 d = *(const int4*)(ei + E + e);
            atomicAdd(&g_cnt[d.x], 1);
            atomicAdd(&g_cnt[d.y], 1);
            atomicAdd(&g_cnt[d.z], 1);
            atomicAdd(&g_cnt[d.w], 1);
        }
    } else {
#pragma unroll
        for (int i = 0; i < 4; i++)
            if (e + i < E) atomicAdd(&g_cnt[ei[E + e + i]], 1);
    }
}

// ---------------- single-block scan (warp-shuffle); restores g_cnt to zero ----------------
__global__ void k_scan(int N) {
    __shared__ int wsum[32];
    int tid = threadIdx.x;
    int lane = tid & 31, wid = tid >> 5;
    int CH = (N + 1023) >> 10;
    int base = tid * CH;
    int s = 0;
    for (int j = 0; j < CH; j++) {
        int i = base + j;
        if (i < N) s += g_cnt[i];
    }
    int v = s;
#pragma unroll
    for (int o = 1; o < 32; o <<= 1) {
        int t = __shfl_up_sync(0xffffffffu, v, o);
        if (lane >= o) v += t;
    }
    if (lane == 31) wsum[wid] = v;
    __syncthreads();
    if (wid == 0) {
        int wv = wsum[lane];
#pragma unroll
        for (int o = 1; o < 32; o <<= 1) {
            int t = __shfl_up_sync(0xffffffffu, wv, o);
            if (lane >= o) wv += t;
        }
        wsum[lane] = wv;
    }
    __syncthreads();
    int run = (v - s) + (wid > 0 ? wsum[wid - 1] : 0);
    for (int j = 0; j < CH; j++) {
        int i = base + j;
        if (i < N) {
            int c = g_cnt[i];
            g_cnt[i] = 0;                       // restore zero invariant
            g_offs[i] = run;
            g_cursor[i] = run;
            g_dis[i] = rsqrtf(1.0f + (float)c);
            run += c;
        }
    }
    if (tid == 1023) g_offs[N] = run;
}

// ---------------- CSR fill (src only; weights computed in agg) ----------------
__global__ void k_csr(const int* __restrict__ ei, int E) {
    int e = blockIdx.x * blockDim.x + threadIdx.x;
    if (e < E) {
        int s = ei[e];
        int d = ei[E + e];
        int pos = atomicAdd(&g_cursor[d], 1);
        g_csr_src[pos] = s;
    }
}

// ---------------- GEMM1 (HMMA): g_hw = x @ W1, fp32 in -> fp16 out (node-major) ----
#define XS1 136
#define CS1 72   // stage stride in halves (144B, 16B-aligned rows)
__global__ void __launch_bounds__(128) k_gemm1(const float* __restrict__ x,
                                               int rows, int N, int B) {
    __shared__ __align__(16) __half Xs[64 * XS1];
    __shared__ __align__(16) __half Wt[64 * XS1];
    __half* Cs = Xs;   // alias: 64*CS1 = 4608 halves <= 64*XS1
    int tid = threadIdx.x;
    size_t r0 = (size_t)blockIdx.x * 64;

    for (int idx = tid; idx < 64 * (FIN / 8); idx += 128) {
        int n = idx >> 4, c = idx & 15;
        *(uint4*)(Wt + n * XS1 + c * 8) = *(const uint4*)(g_w1t + n * FIN + c * 8);
    }
    for (int idx = tid; idx < 64 * (FIN / 4); idx += 128) {
        int row = idx >> 5, c = idx & 31;
        size_t r = r0 + row;
        float4 v = make_float4(0.f, 0.f, 0.f, 0.f);
        if (r < (size_t)rows) v = *(const float4*)(x + r * FIN + c * 4);
        __half2* p = (__half2*)(Xs + row * XS1 + c * 4);
        p[0] = __floats2half2_rn(v.x, v.y);
        p[1] = __floats2half2_rn(v.z, v.w);
    }
    __syncthreads();

    int wid = tid >> 5, lane = tid & 31;
    int gid = lane >> 2, tig = lane & 3;
    const __half* A0 = Xs + (wid * 16 + gid) * XS1 + 2 * tig;
    const __half* A1 = A0 + 8 * XS1;

    float acc[8][4];
#pragma unroll
    for (int i = 0; i < 8; i++)
#pragma unroll
        for (int j = 0; j < 4; j++) acc[i][j] = 0.f;

#pragma unroll
    for (int ks = 0; ks < FIN / 16; ks++) {
        int k0 = ks * 16;
        uint32_t a0 = *(const uint32_t*)(A0 + k0);
        uint32_t a1 = *(const uint32_t*)(A1 + k0);
        uint32_t a2 = *(const uint32_t*)(A0 + k0 + 8);
        uint32_t a3 = *(const uint32_t*)(A1 + k0 + 8);
#pragma unroll
        for (int nt = 0; nt < 8; nt++) {
            const __half* Bp = Wt + (nt * 8 + gid) * XS1 + k0 + 2 * tig;
            uint32_t b0 = *(const uint32_t*)(Bp);
            uint32_t b1 = *(const uint32_t*)(Bp + 8);
            mma16816(acc[nt], a0, a1, a2, a3, b0, b1);
        }
    }

    __syncthreads();   // all reads of Xs done; safe to overwrite as Cs
    {
        int row1 = wid * 16 + gid, row2 = row1 + 8;
#pragma unroll
        for (int nt = 0; nt < 8; nt++) {
            *(__half2*)(Cs + row1 * CS1 + nt * 8 + 2 * tig) =
                __floats2half2_rn(acc[nt][0], acc[nt][1]);
            *(__half2*)(Cs + row2 * CS1 + nt * 8 + 2 * tig) =
                __floats2half2_rn(acc[nt][2], acc[nt][3]);
        }
    }
    __syncthreads();
    for (int idx = tid; idx < 64 * 8; idx += 128) {
        int row = idx >> 3, c = idx & 7;
        size_t r = r0 + row;
        if (r < (size_t)rows) {
            int n = (int)(r % N), b = (int)(r / N);
            *(uint4*)(g_hw + ((size_t)n * B + b) * HID + c * 8) =
                *(const uint4*)(Cs + row * CS1 + c * 8);
        }
    }
}

// ---------------- GEMM2 (HMMA): g_f8 = h1 @ W2, fp16 in -> fp8 out (node-major) ----
#define XS2 72
#define CS2 80   // fp8 stage stride in BYTES (16B-aligned rows)
__global__ void __launch_bounds__(128) k_gemm2(int rows) {
    __shared__ __align__(16) __half Xs[64 * XS2];
    __shared__ __align__(16) __half Wt[64 * XS2];
    unsigned char* Cs = (unsigned char*)Xs;   // alias: 64*CS2 = 5120B <= 9216B
    int tid = threadIdx.x;
    size_t r0 = (size_t)blockIdx.x * 64;

    for (int idx = tid; idx < 64 * (HID / 8); idx += 128) {
        int n = idx >> 3, c = idx & 7;
        *(uint4*)(Wt + n * XS2 + c * 8) = *(const uint4*)(g_w2t + n * HID + c * 8);
    }
    for (int idx = tid; idx < 64 * (HID / 8); idx += 128) {
        int row = idx >> 3, c = idx & 7;
        size_t r = r0 + row;
        uint4 v = make_uint4(0u, 0u, 0u, 0u);
        if (r < (size_t)rows) v = *(const uint4*)(g_h1 + r * HID + c * 8);
        *(uint4*)(Xs + row * XS2 + c * 8) = v;
    }
    __syncthreads();

    int wid = tid >> 5, lane = tid & 31;
    int gid = lane >> 2, tig = lane & 3;
    const __half* A0 = Xs + (wid * 16 + gid) * XS2 + 2 * tig;
    const __half* A1 = A0 + 8 * XS2;

    float acc[8][4];
#pragma unroll
    for (int i = 0; i < 8; i++)
#pragma unroll
        for (int j = 0; j < 4; j++) acc[i][j] = 0.f;

#pragma unroll
    for (int ks = 0; ks < HID / 16; ks++) {
        int k0 = ks * 16;
        uint32_t a0 = *(const uint32_t*)(A0 + k0);
        uint32_t a1 = *(const uint32_t*)(A1 + k0);
        uint32_t a2 = *(const uint32_t*)(A0 + k0 + 8);
        uint32_t a3 = *(const uint32_t*)(A1 + k0 + 8);
#pragma unroll
        for (int nt = 0; nt < 8; nt++) {
            const __half* Bp = Wt + (nt * 8 + gid) * XS2 + k0 + 2 * tig;
            uint32_t b0 = *(const uint32_t*)(Bp);
            uint32_t b1 = *(const uint32_t*)(Bp + 8);
            mma16816(acc[nt], a0, a1, a2, a3, b0, b1);
        }
    }

    __syncthreads();   // Xs reads done; reuse as Cs
    {
        int row1 = wid * 16 + gid, row2 = row1 + 8;
#pragma unroll
        for (int nt = 0; nt < 8; nt++) {
            *(unsigned short*)(Cs + row1 * CS2 + nt * 8 + 2 * tig) =
                f2_to_f8x2(acc[nt][0], acc[nt][1]);
            *(unsigned short*)(Cs + row2 * CS2 + nt * 8 + 2 * tig) =
                f2_to_f8x2(acc[nt][2], acc[nt][3]);
        }
    }
    __syncthreads();
    for (int idx = tid; idx < 64 * 4; idx += 128) {
        int row = idx >> 2, c = idx & 3;
        size_t r = r0 + row;
        if (r < (size_t)rows)
            *(uint4*)(g_f8 + r * HID + c * 16) = *(const uint4*)(Cs + row * CS2 + c * 16);
    }
}

// ---------------- layer-1 aggregation (fp16 NC gather, pipelined 4-unroll) -> g_h1 ----
__global__ void __launch_bounds__(256) k_agg1(const float* __restrict__ bias,
                                              int N, int Bsz) {
    int lt = threadIdx.x & 63;
    int node = blockIdx.x * 4 + (threadIdx.x >> 6);
    if (node >= N) return;
    int f = lt * 8;
    int rowlen = Bsz * HID;
    if (f >= rowlen) return;
    int h = f & (HID - 1);
    float dn = g_dis[node];
    float sn = dn * dn;
    size_t base = (size_t)node * rowlen;

    float acc[8];
    {
        uint4 sv = __ldg((const uint4*)(g_hw + base + f));
        const __half2* hp = (const __half2*)&sv;
#pragma unroll
        for (int j = 0; j < 4; j++) {
            float2 a = __half22float2(hp[j]);
            acc[j * 2]     = fmaf(a.x, sn, bias[h + j * 2]);
            acc[j * 2 + 1] = fmaf(a.y, sn, bias[h + j * 2 + 1]);
        }
    }

    int e = g_offs[node], e1 = g_offs[node + 1];
    if (e + 3 < e1) {
        // prime the index/weight pipeline
        int s0 = g_csr_src[e], s1 = g_csr_src[e + 1];
        int s2 = g_csr_src[e + 2], s3 = g_csr_src[e + 3];
        float w0 = g_dis[s0] * dn, w1 = g_dis[s1] * dn;
        float w2 = g_dis[s2] * dn, w3 = g_dis[s3] * dn;
        for (; e + 7 < e1; e += 4) {
            // gathers for the current quad
            uint4 p0 = __ldg((const uint4*)(g_hw + (size_t)s0 * rowlen + f));
            uint4 p1 = __ldg((const uint4*)(g_hw + (size_t)s1 * rowlen + f));
            uint4 p2 = __ldg((const uint4*)(g_hw + (size_t)s2 * rowlen + f));
            uint4 p3 = __ldg((const uint4*)(g_hw + (size_t)s3 * rowlen + f));
            // prefetch the next quad's indices+weights while gathers are in flight
            int t0 = g_csr_src[e + 4], t1 = g_csr_src[e + 5];
            int t2 = g_csr_src[e + 6], t3 = g_csr_src[e + 7];
            float v0 = g_dis[t0] * dn, v1 = g_dis[t1] * dn;
            float v2 = g_dis[t2] * dn, v3 = g_dis[t3] * dn;
            const __half2* q0 = (const __half2*)&p0;
            const __half2* q1 = (const __half2*)&p1;
            const __half2* q2 = (const __half2*)&p2;
            const __half2* q3 = (const __half2*)&p3;
#pragma unroll
            for (int j = 0; j < 4; j++) {
                float2 a;
                a = __half22float2(q0[j]);
                acc[j*2] = fmaf(w0, a.x, acc[j*2]); acc[j*2+1] = fmaf(w0, a.y, acc[j*2+1]);
                a = __half22float2(q1[j]);
                acc[j*2] = fmaf(w1, a.x, acc[j*2]); acc[j*2+1] = fmaf(w1, a.y, acc[j*2+1]);
                a = __half22float2(q2[j]);
                acc[j*2] = fmaf(w2, a.x, acc[j*2]); acc[j*2+1] = fmaf(w2, a.y, acc[j*2+1]);
                a = __half22float2(q3[j]);
                acc[j*2] = fmaf(w3, a.x, acc[j*2]); acc[j*2+1] = fmaf(w3, a.y, acc[j*2+1]);
            }
            s0 = t0; s1 = t1; s2 = t2; s3 = t3;
            w0 = v0; w1 = v1; w2 = v2; w3 = v3;
        }
        // drain the primed quad
        {
            uint4 p0 = __ldg((const uint4*)(g_hw + (size_t)s0 * rowlen + f));
            uint4 p1 = __ldg((const uint4*)(g_hw + (size_t)s1 * rowlen + f));
            uint4 p2 = __ldg((const uint4*)(g_hw + (size_t)s2 * rowlen + f));
            uint4 p3 = __ldg((const uint4*)(g_hw + (size_t)s3 * rowlen + f));
            const __half2* q0 = (const __half2*)&p0;
            const __half2* q1 = (const __half2*)&p1;
            const __half2* q2 = (const __half2*)&p2;
            const __half2* q3 = (const __half2*)&p3;
#pragma unroll
            for (int j = 0; j < 4; j++) {
                float2 a;
                a = __half22float2(q0[j]);
                acc[j*2] = fmaf(w0, a.x, acc[j*2]); acc[j*2+1] = fmaf(w0, a.y, acc[j*2+1]);
                a = __half22float2(q1[j]);
                acc[j*2] = fmaf(w1, a.x, acc[j*2]); acc[j*2+1] = fmaf(w1, a.y, acc[j*2+1]);
                a = __half22float2(q2[j]);
                acc[j*2] = fmaf(w2, a.x, acc[j*2]); acc[j*2+1] = fmaf(w2, a.y, acc[j*2+1]);
                a = __half22float2(q3[j]);
                acc[j*2] = fmaf(w3, a.x, acc[j*2]); acc[j*2+1] = fmaf(w3, a.y, acc[j*2+1]);
            }
            e += 4;
        }
    }
    for (; e < e1; e++) {
        int s0 = g_csr_src[e];
        float w0 = g_dis[s0] * dn;
        uint4 p0 = __ldg((const uint4*)(g_hw + (size_t)s0 * rowlen + f));
        const __half2* q0 = (const __half2*)&p0;
#pragma unroll
        for (int j = 0; j < 4; j++) {
            float2 a = __half22float2(q0[j]);
            acc[j * 2] = fmaf(w0, a.x, acc[j * 2]); acc[j * 2 + 1] = fmaf(w0, a.y, acc[j * 2 + 1]);
        }
    }
    uint4 st;
    __half2* so = (__half2*)&st;
#pragma unroll
    for (int j = 0; j < 4; j++)
        so[j] = __floats2half2_rn(fmaxf(acc[j * 2], 0.f), fmaxf(acc[j * 2 + 1], 0.f));
    *(uint4*)(g_h1 + base + f) = st;
}

// ---------------- layer-2 aggregation (fp8 NC gather, pipelined) + fc dot + pool + final ----
__global__ void __launch_bounds__(256) k_agg2(const float* __restrict__ bias,
                                              const float* __restrict__ fcw,
                                              const float* __restrict__ fcb,
                                              const float* __restrict__ add,
                                              float* __restrict__ out,
                                              int N, int Bsz) {
    int lt = threadIdx.x & 63;
    int node = blockIdx.x * 4 + (threadIdx.x >> 6);
    int f = lt * 8;
    int rowlen = Bsz * HID;
    bool active = (node < N) && (f < rowlen);

    if (active) {
        int h = f & (HID - 1);
        float dn = g_dis[node];
        float sn = dn * dn;
        size_t base = (size_t)node * rowlen;

        float acc[8];
        {
            uint2 sv = __ldg((const uint2*)(g_f8 + base + f));
            float4 a = f8x4_to_f4(sv.x), b = f8x4_to_f4(sv.y);
            acc[0] = fmaf(a.x, sn, bias[h]);     acc[1] = fmaf(a.y, sn, bias[h + 1]);
            acc[2] = fmaf(a.z, sn, bias[h + 2]); acc[3] = fmaf(a.w, sn, bias[h + 3]);
            acc[4] = fmaf(b.x, sn, bias[h + 4]); acc[5] = fmaf(b.y, sn, bias[h + 5]);
            acc[6] = fmaf(b.z, sn, bias[h + 6]); acc[7] = fmaf(b.w, sn, bias[h + 7]);
        }

        int e = g_offs[node], e1 = g_offs[node + 1];
        if (e + 3 < e1) {
            int s0 = g_csr_src[e], s1 = g_csr_src[e + 1];
            int s2 = g_csr_src[e + 2], s3 = g_csr_src[e + 3];
            float w0 = g_dis[s0] * dn, w1 = g_dis[s1] * dn;
            float w2 = g_dis[s2] * dn, w3 = g_dis[s3] * dn;
            for (; e + 7 < e1; e += 4) {
                uint2 p0 = __ldg((const uint2*)(g_f8 + (size_t)s0 * rowlen + f));
                uint2 p1 = __ldg((const uint2*)(g_f8 + (size_t)s1 * rowlen + f));
                uint2 p2 = __ldg((const uint2*)(g_f8 + (size_t)s2 * rowlen + f));
                uint2 p3 = __ldg((const uint2*)(g_f8 + (size_t)s3 * rowlen + f));
                int t0 = g_csr_src[e + 4], t1 = g_csr_src[e + 5];
                int t2 = g_csr_src[e + 6], t3 = g_csr_src[e + 7];
                float v0 = g_dis[t0] * dn, v1 = g_dis[t1] * dn;
                float v2 = g_dis[t2] * dn, v3 = g_dis[t3] * dn;
#pragma unroll
                for (int j = 0; j < 2; j++) {
                    float4 m;
                    m = f8x4_to_f4(j ? p0.y : p0.x);
                    acc[j*4+0] = fmaf(w0, m.x, acc[j*4+0]); acc[j*4+1] = fmaf(w0, m.y, acc[j*4+1]);
                    acc[j*4+2] = fmaf(w0, m.z, acc[j*4+2]); acc[j*4+3] = fmaf(w0, m.w, acc[j*4+3]);
                    m = f8x4_to_f4(j ? p1.y : p1.x);
                    acc[j*4+0] = fmaf(w1, m.x, acc[j*4+0]); acc[j*4+1] = fmaf(w1, m.y, acc[j*4+1]);
                    acc[j*4+2] = fmaf(w1, m.z, acc[j*4+2]); acc[j*4+3] = fmaf(w1, m.w, acc[j*4+3]);
                    m = f8x4_to_f4(j ? p2.y : p2.x);
                    acc[j*4+0] = fmaf(w2, m.x, acc[j*4+0]); acc[j*4+1] = fmaf(w2, m.y, acc[j*4+1]);
                    acc[j*4+2] = fmaf(w2, m.z, acc[j*4+2]); acc[j*4+3] = fmaf(w2, m.w, acc[j*4+3]);
                    m = f8x4_to_f4(j ? p3.y : p3.x);
                    acc[j*4+0] = fmaf(w3, m.x, acc[j*4+0]); acc[j*4+1] = fmaf(w3, m.y, acc[j*4+1]);
                    acc[j*4+2] = fmaf(w3, m.z, acc[j*4+2]); acc[j*4+3] = fmaf(w3, m.w, acc[j*4+3]);
                }
                s0 = t0; s1 = t1; s2 = t2; s3 = t3;
                w0 = v0; w1 = v1; w2 = v2; w3 = v3;
            }
            {
                uint2 p0 = __ldg((const uint2*)(g_f8 + (size_t)s0 * rowlen + f));
                uint2 p1 = __ldg((const uint2*)(g_f8 + (size_t)s1 * rowlen + f));
                uint2 p2 = __ldg((const uint2*)(g_f8 + (size_t)s2 * rowlen + f));
                uint2 p3 = __ldg((const uint2*)(g_f8 + (size_t)s3 * rowlen + f));
#pragma unroll
                for (int j = 0; j < 2; j++) {
                    float4 m;
                    m = f8x4_to_f4(j ? p0.y : p0.x);
                    acc[j*4+0] = fmaf(w0, m.x, acc[j*4+0]); acc[j*4+1] = fmaf(w0, m.y, acc[j*4+1]);
                    acc[j*4+2] = fmaf(w0, m.z, acc[j*4+2]); acc[j*4+3] = fmaf(w0, m.w, acc[j*4+3]);
                    m = f8x4_to_f4(j ? p1.y : p1.x);
                    acc[j*4+0] = fmaf(w1, m.x, acc[j*4+0]); acc[j*4+1] = fmaf(w1, m.y, acc[j*4+1]);
                    acc[j*4+2] = fmaf(w1, m.z, acc[j*4+2]); acc[j*4+3] = fmaf(w1, m.w, acc[j*4+3]);
                    m = f8x4_to_f4(j ? p2.y : p2.x);
                    acc[j*4+0] = fmaf(w2, m.x, acc[j*4+0]); acc[j*4+1] = fmaf(w2, m.y, acc[j*4+1]);
                    acc[j*4+2] = fmaf(w2, m.z, acc[j*4+2]); acc[j*4+3] = fmaf(w2, m.w, acc[j*4+3]);
                    m = f8x4_to_f4(j ? p3.y : p3.x);
                    acc[j*4+0] = fmaf(w3, m.x, acc[j*4+0]); acc[j*4+1] = fmaf(w3, m.y, acc[j*4+1]);
                    acc[j*4+2] = fmaf(w3, m.z, acc[j*4+2]); acc[j*4+3] = fmaf(w3, m.w, acc[j*4+3]);
                }
                e += 4;
            }
        }
        for (; e < e1; e++) {
            int s0 = g_csr_src[e];
            float w0 = g_dis[s0] * dn;
            uint2 p0 = __ldg((const uint2*)(g_f8 + (size_t)s0 * rowlen + f));
#pragma unroll
            for (int j = 0; j < 2; j++) {
                float4 m = f8x4_to_f4(j ? p0.y : p0.x);
                acc[j*4+0] = fmaf(w0, m.x, acc[j*4+0]); acc[j*4+1] = fmaf(w0, m.y, acc[j*4+1]);
                acc[j*4+2] = fmaf(w0, m.z, acc[j*4+2]); acc[j*4+3] = fmaf(w0, m.w, acc[j*4+3]);
            }
        }

        int h0 = f & (HID - 1);
        float c = 0.f;
#pragma unroll
        for (int j = 0; j < 8; j++) c = fmaf(fmaxf(acc[j], 0.f), fcw[h0 + j], c);
#pragma unroll
        for (int o = 4; o; o >>= 1) c += __shfl_xor_sync(0xffffffffu, c, o);
        if ((threadIdx.x & 7) == 0) {
            int b = lt >> 3;
            atomicAdd(&g_partial[b * 64 + (node & 63)], c);
        }
    }

    // -------- tail-block fused final reduce --------
    __shared__ bool isLast;
    if (threadIdx.x == 0) {
        __threadfence();
        unsigned int t = atomicAdd(&g_done, 1u);
        isLast = (t == gridDim.x - 1);
    }
    __syncthreads();
    if (isLast) {
        __threadfence();
        int b = threadIdx.x >> 5;
        int lane = threadIdx.x & 31;
        float s = 0.f;
        if (b < Bsz)
            s = g_partial[b * 64 + lane] + g_partial[b * 64 + 32 + lane];
#pragma unroll
        for (int o = 16; o; o >>= 1) s += __shfl_xor_sync(0xffffffffu, s, o);
        if (b < Bsz && lane == 0)
            out[b] = s * (1.0f / (float)N) + add[b] * fcw[HID] + fcb[0];
        __syncthreads();
        for (int i = threadIdx.x; i < MAXB * 64; i += 256) g_partial[i] = 0.f;
        if (threadIdx.x == 0) g_done = 0u;
    }
}

// ---------------- launch ----------------
extern "C" void kernel_launch(void* const* d_in, const int* in_sizes, int n_in,
                              void* d_out, int out_size) {
    const float* x   = (const float*)d_in[0];
    const float* add = (const float*)d_in[1];
    const int*   ei  = (const int*)d_in[2];
    const float* W1  = (const float*)d_in[3];
    const float* b1  = (const float*)d_in[4];
    const float* W2  = (const float*)d_in[5];
    const float* b2  = (const float*)d_in[6];
    const float* fcw = (const float*)d_in[7];
    const float* fcb = (const float*)d_in[8];
    float* out = (float*)d_out;

    int B = in_sizes[1];
    int E = in_sizes[2] / 2;
    int N = in_sizes[0] / (B * FIN);
    int rows = B * N;

    static cudaStream_t s_side = nullptr;
    static cudaEvent_t ev_fork = nullptr, ev_join = nullptr;
    if (s_side == nullptr) {
        cudaStreamCreateWithFlags(&s_side, cudaStreamNonBlocking);
        cudaEventCreateWithFlags(&ev_fork, cudaEventDisableTiming);
        cudaEventCreateWithFlags(&ev_join, cudaEventDisableTiming);
    }

    // fork: graph structure (needs only edge_index) beside wconv+gemm1
    cudaEventRecord(ev_fork, 0);
    cudaStreamWaitEvent(s_side, ev_fork, 0);
    k_count<<<(E / 4 + 256) / 256, 256, 0, s_side>>>(ei, E);
    k_scan<<<1, 1024, 0, s_side>>>(N);
    k_csr<<<(E + 255) / 256, 256, 0, s_side>>>(ei, E);
    cudaEventRecord(ev_join, s_side);

    k_wconv<<<(FIN * HID + HID * HID + 255) / 256, 256>>>(W1, W2);
    k_gemm1<<<(rows + 63) / 64, 128>>>(x, rows, N, B);

    // join: agg1 needs both csr and gemm1 output
    cudaStreamWaitEvent(0, ev_join, 0);
    k_agg1<<<(N + 3) / 4, 256>>>(b1, N, B);
    k_gemm2<<<(rows + 63) / 64, 128>>>(rows);
    k_agg2<<<(N + 3) / 4, 256>>>(b2, fcw, fcb, add, out, N, B);
}

// round 17
// speedup vs baseline: 1.3189x; 1.3189x over previous
#include <cuda_runtime.h>
#include <cuda_fp16.h>
#include <cuda_fp8.h>
#include <cstdint>

#define MAXN 20000
#define MAXE 320000
#define FIN  128
#define HID  64
#define MAXB 8

// ---------------- static device scratch (allocation-free rule) ----------------
// Invariant: g_cnt, g_partial, g_done are ZERO at kernel_launch entry.
__device__ __align__(16) __half g_hw[(size_t)MAXN * MAXB * HID];        // layer-1 feats, fp16, node-major
__device__ __align__(16) __half g_h1[(size_t)MAXN * MAXB * HID];        // layer-1 activations, fp16
__device__ __align__(16) unsigned char g_f8[(size_t)MAXN * MAXB * HID]; // layer-2 feats, fp8
__device__ __half g_w1t[FIN * HID];                                      // W1^T fp16 [n][k]
__device__ __half g_w2t[HID * HID];                                      // W2^T fp16 [n][k]
__device__ int    g_cnt[MAXN];
__device__ int    g_offs[MAXN + 1];
__device__ int    g_cursor[MAXN];
__device__ float  g_dis[MAXN];
__device__ int    g_csr_src[MAXE];
__device__ float  g_partial[MAXB * 64];
__device__ unsigned int g_done;

// ---------------- fp8 helpers ----------------
__device__ __forceinline__ float4 f8x4_to_f4(uint32_t p) {
    __half2_raw lo = __nv_cvt_fp8x2_to_halfraw2((__nv_fp8x2_storage_t)(p & 0xffffu), __NV_E4M3);
    __half2_raw hi = __nv_cvt_fp8x2_to_halfraw2((__nv_fp8x2_storage_t)(p >> 16), __NV_E4M3);
    float2 a = __half22float2(*(__half2*)&lo);
    float2 b = __half22float2(*(__half2*)&hi);
    return make_float4(a.x, a.y, b.x, b.y);
}
__device__ __forceinline__ unsigned short f2_to_f8x2(float a, float b) {
    return (unsigned short)__nv_cvt_float2_to_fp8x2(make_float2(a, b), __NV_SATFINITE, __NV_E4M3);
}

// ---------------- HMMA m16n8k16 fp16 -> fp32 ----------------
__device__ __forceinline__ void mma16816(float* c, uint32_t a0, uint32_t a1,
                                         uint32_t a2, uint32_t a3,
                                         uint32_t b0, uint32_t b1) {
    asm volatile(
        "mma.sync.aligned.m16n8k16.row.col.f32.f16.f16.f32 "
        "{%0,%1,%2,%3}, {%4,%5,%6,%7}, {%8,%9}, {%0,%1,%2,%3};"
        : "+f"(c[0]), "+f"(c[1]), "+f"(c[2]), "+f"(c[3])
        : "r"(a0), "r"(a1), "r"(a2), "r"(a3), "r"(b0), "r"(b1));
}

// ---------------- weight convert + transpose (once; separate kernel on purpose:
// in-GEMM transpose causes 16-way STS conflicts with the MMA-friendly stride) ----
__global__ void k_wconv(const float* __restrict__ W1, const float* __restrict__ W2) {
    int i = blockIdx.x * blockDim.x + threadIdx.x;
    if (i < FIN * HID) {
        int k = i >> 6, n = i & 63;
        g_w1t[n * FIN + k] = __float2half_rn(W1[i]);
    } else if (i < FIN * HID + HID * HID) {
        int j = i - FIN * HID;
        int k = j >> 6, n = j & 63;
        g_w2t[n * HID + k] = __float2half_rn(W2[j]);
    }
}

// ---------------- in-degree count (g_cnt zero on entry by invariant) ----------------
__global__ void k_count(const int* __restrict__ ei, int E) {
    int t = blockIdx.x * blockDim.x + threadIdx.x;
    int e = t * 4;
    if ((E & 3) == 0) {
        if (e < E) {
            int4 d = *(const int4*)(ei + E + e);
            atomicAdd(&g_cnt[d.x], 1);
            atomicAdd(&g_cnt[d.y], 1);
            atomicAdd(&g_cnt[d.z], 1);
            atomicAdd(&g_cnt[d.w], 1);
        }
    } else {
#pragma unroll
        for (int i = 0; i < 4; i++)
            if (e + i < E) atomicAdd(&g_cnt[ei[E + e + i]], 1);
    }
}

// ---------------- single-block scan (warp-shuffle); restores g_cnt to zero ----------------
__global__ void k_scan(int N) {
    __shared__ int wsum[32];
    int tid = threadIdx.x;
    int lane = tid & 31, wid = tid >> 5;
    int CH = (N + 1023) >> 10;
    int base = tid * CH;
    int s = 0;
    for (int j = 0; j < CH; j++) {
        int i = base + j;
        if (i < N) s += g_cnt[i];
    }
    int v = s;
#pragma unroll
    for (int o = 1; o < 32; o <<= 1) {
        int t = __shfl_up_sync(0xffffffffu, v, o);
        if (lane >= o) v += t;
    }
    if (lane == 31) wsum[wid] = v;
    __syncthreads();
    if (wid == 0) {
        int wv = wsum[lane];
#pragma unroll
        for (int o = 1; o < 32; o <<= 1) {
            int t = __shfl_up_sync(0xffffffffu, wv, o);
            if (lane >= o) wv += t;
        }
        wsum[lane] = wv;
    }
    __syncthreads();
    int run = (v - s) + (wid > 0 ? wsum[wid - 1] : 0);
    for (int j = 0; j < CH; j++) {
        int i = base + j;
        if (i < N) {
            int c = g_cnt[i];
            g_cnt[i] = 0;                       // restore zero invariant
            g_offs[i] = run;
            g_cursor[i] = run;
            g_dis[i] = rsqrtf(1.0f + (float)c);
            run += c;
        }
    }
    if (tid == 1023) g_offs[N] = run;
}

// ---------------- CSR fill (src only; weights computed in agg) ----------------
__global__ void k_csr(const int* __restrict__ ei, int E) {
    int e = blockIdx.x * blockDim.x + threadIdx.x;
    if (e < E) {
        int s = ei[e];
        int d = ei[E + e];
        int pos = atomicAdd(&g_cursor[d], 1);
        g_csr_src[pos] = s;
    }
}

// ---------------- GEMM1 (HMMA): g_hw = x @ W1, fp32 in -> fp16 out (node-major) ----
#define XS1 136
#define CS1 72   // stage stride in halves (144B, 16B-aligned rows)
__global__ void __launch_bounds__(128) k_gemm1(const float* __restrict__ x,
                                               int rows, int N, int B) {
    __shared__ __align__(16) __half Xs[64 * XS1];
    __shared__ __align__(16) __half Wt[64 * XS1];
    __half* Cs = Xs;   // alias: 64*CS1 = 4608 halves <= 64*XS1
    int tid = threadIdx.x;
    size_t r0 = (size_t)blockIdx.x * 64;

    for (int idx = tid; idx < 64 * (FIN / 8); idx += 128) {
        int n = idx >> 4, c = idx & 15;
        *(uint4*)(Wt + n * XS1 + c * 8) = *(const uint4*)(g_w1t + n * FIN + c * 8);
    }
    for (int idx = tid; idx < 64 * (FIN / 4); idx += 128) {
        int row = idx >> 5, c = idx & 31;
        size_t r = r0 + row;
        float4 v = make_float4(0.f, 0.f, 0.f, 0.f);
        if (r < (size_t)rows) v = *(const float4*)(x + r * FIN + c * 4);
        __half2* p = (__half2*)(Xs + row * XS1 + c * 4);
        p[0] = __floats2half2_rn(v.x, v.y);
        p[1] = __floats2half2_rn(v.z, v.w);
    }
    __syncthreads();

    int wid = tid >> 5, lane = tid & 31;
    int gid = lane >> 2, tig = lane & 3;
    const __half* A0 = Xs + (wid * 16 + gid) * XS1 + 2 * tig;
    const __half* A1 = A0 + 8 * XS1;

    float acc[8][4];
#pragma unroll
    for (int i = 0; i < 8; i++)
#pragma unroll
        for (int j = 0; j < 4; j++) acc[i][j] = 0.f;

#pragma unroll
    for (int ks = 0; ks < FIN / 16; ks++) {
        int k0 = ks * 16;
        uint32_t a0 = *(const uint32_t*)(A0 + k0);
        uint32_t a1 = *(const uint32_t*)(A1 + k0);
        uint32_t a2 = *(const uint32_t*)(A0 + k0 + 8);
        uint32_t a3 = *(const uint32_t*)(A1 + k0 + 8);
#pragma unroll
        for (int nt = 0; nt < 8; nt++) {
            const __half* Bp = Wt + (nt * 8 + gid) * XS1 + k0 + 2 * tig;
            uint32_t b0 = *(const uint32_t*)(Bp);
            uint32_t b1 = *(const uint32_t*)(Bp + 8);
            mma16816(acc[nt], a0, a1, a2, a3, b0, b1);
        }
    }

    __syncthreads();   // all reads of Xs done; safe to overwrite as Cs
    {
        int row1 = wid * 16 + gid, row2 = row1 + 8;
#pragma unroll
        for (int nt = 0; nt < 8; nt++) {
            *(__half2*)(Cs + row1 * CS1 + nt * 8 + 2 * tig) =
                __floats2half2_rn(acc[nt][0], acc[nt][1]);
            *(__half2*)(Cs + row2 * CS1 + nt * 8 + 2 * tig) =
                __floats2half2_rn(acc[nt][2], acc[nt][3]);
        }
    }
    __syncthreads();
    for (int idx = tid; idx < 64 * 8; idx += 128) {
        int row = idx >> 3, c = idx & 7;
        size_t r = r0 + row;
        if (r < (size_t)rows) {
            int n = (int)(r % N), b = (int)(r / N);
            *(uint4*)(g_hw + ((size_t)n * B + b) * HID + c * 8) =
                *(const uint4*)(Cs + row * CS1 + c * 8);
        }
    }
}

// ---------------- GEMM2 (HMMA): g_f8 = h1 @ W2, fp16 in -> fp8 out (node-major) ----
#define XS2 72
#define CS2 80   // fp8 stage stride in BYTES (16B-aligned rows)
__global__ void __launch_bounds__(128) k_gemm2(int rows) {
    __shared__ __align__(16) __half Xs[64 * XS2];
    __shared__ __align__(16) __half Wt[64 * XS2];
    unsigned char* Cs = (unsigned char*)Xs;   // alias: 64*CS2 = 5120B <= 9216B
    int tid = threadIdx.x;
    size_t r0 = (size_t)blockIdx.x * 64;

    for (int idx = tid; idx < 64 * (HID / 8); idx += 128) {
        int n = idx >> 3, c = idx & 7;
        *(uint4*)(Wt + n * XS2 + c * 8) = *(const uint4*)(g_w2t + n * HID + c * 8);
    }
    for (int idx = tid; idx < 64 * (HID / 8); idx += 128) {
        int row = idx >> 3, c = idx & 7;
        size_t r = r0 + row;
        uint4 v = make_uint4(0u, 0u, 0u, 0u);
        if (r < (size_t)rows) v = *(const uint4*)(g_h1 + r * HID + c * 8);
        *(uint4*)(Xs + row * XS2 + c * 8) = v;
    }
    __syncthreads();

    int wid = tid >> 5, lane = tid & 31;
    int gid = lane >> 2, tig = lane & 3;
    const __half* A0 = Xs + (wid * 16 + gid) * XS2 + 2 * tig;
    const __half* A1 = A0 + 8 * XS2;

    float acc[8][4];
#pragma unroll
    for (int i = 0; i < 8; i++)
#pragma unroll
        for (int j = 0; j < 4; j++) acc[i][j] = 0.f;

#pragma unroll
    for (int ks = 0; ks < HID / 16; ks++) {
        int k0 = ks * 16;
        uint32_t a0 = *(const uint32_t*)(A0 + k0);
        uint32_t a1 = *(const uint32_t*)(A1 + k0);
        uint32_t a2 = *(const uint32_t*)(A0 + k0 + 8);
        uint32_t a3 = *(const uint32_t*)(A1 + k0 + 8);
#pragma unroll
        for (int nt = 0; nt < 8; nt++) {
            const __half* Bp = Wt + (nt * 8 + gid) * XS2 + k0 + 2 * tig;
            uint32_t b0 = *(const uint32_t*)(Bp);
            uint32_t b1 = *(const uint32_t*)(Bp + 8);
            mma16816(acc[nt], a0, a1, a2, a3, b0, b1);
        }
    }

    __syncthreads();   // Xs reads done; reuse as Cs
    {
        int row1 = wid * 16 + gid, row2 = row1 + 8;
#pragma unroll
        for (int nt = 0; nt < 8; nt++) {
            *(unsigned short*)(Cs + row1 * CS2 + nt * 8 + 2 * tig) =
                f2_to_f8x2(acc[nt][0], acc[nt][1]);
            *(unsigned short*)(Cs + row2 * CS2 + nt * 8 + 2 * tig) =
                f2_to_f8x2(acc[nt][2], acc[nt][3]);
        }
    }
    __syncthreads();
    for (int idx = tid; idx < 64 * 4; idx += 128) {
        int row = idx >> 2, c = idx & 3;
        size_t r = r0 + row;
        if (r < (size_t)rows)
            *(uint4*)(g_f8 + r * HID + c * 16) = *(const uint4*)(Cs + row * CS2 + c * 16);
    }
}

// ---------------- layer-1 aggregation (fp16 NC gather, 4-edge unroll) -> g_h1 ----------------
__global__ void __launch_bounds__(256) k_agg1(const float* __restrict__ bias,
                                              int N, int Bsz) {
    int lt = threadIdx.x & 63;
    int node = blockIdx.x * 4 + (threadIdx.x >> 6);
    if (node >= N) return;
    int f = lt * 8;
    int rowlen = Bsz * HID;
    if (f >= rowlen) return;
    int h = f & (HID - 1);
    float dn = g_dis[node];
    float sn = dn * dn;
    size_t base = (size_t)node * rowlen;

    float acc[8];
    {
        uint4 sv = __ldg((const uint4*)(g_hw + base + f));
        const __half2* hp = (const __half2*)&sv;
#pragma unroll
        for (int j = 0; j < 4; j++) {
            float2 a = __half22float2(hp[j]);
            acc[j * 2]     = fmaf(a.x, sn, bias[h + j * 2]);
            acc[j * 2 + 1] = fmaf(a.y, sn, bias[h + j * 2 + 1]);
        }
    }

    int e = g_offs[node], e1 = g_offs[node + 1];
    for (; e + 3 < e1; e += 4) {
        int s0 = g_csr_src[e], s1 = g_csr_src[e + 1];
        int s2 = g_csr_src[e + 2], s3 = g_csr_src[e + 3];
        float w0 = g_dis[s0] * dn, w1 = g_dis[s1] * dn;
        float w2 = g_dis[s2] * dn, w3 = g_dis[s3] * dn;
        uint4 p0 = __ldg((const uint4*)(g_hw + (size_t)s0 * rowlen + f));
        uint4 p1 = __ldg((const uint4*)(g_hw + (size_t)s1 * rowlen + f));
        uint4 p2 = __ldg((const uint4*)(g_hw + (size_t)s2 * rowlen + f));
        uint4 p3 = __ldg((const uint4*)(g_hw + (size_t)s3 * rowlen + f));
        const __half2* q0 = (const __half2*)&p0;
        const __half2* q1 = (const __half2*)&p1;
        const __half2* q2 = (const __half2*)&p2;
        const __half2* q3 = (const __half2*)&p3;
#pragma unroll
        for (int j = 0; j < 4; j++) {
            float2 a;
            a = __half22float2(q0[j]);
            acc[j * 2] = fmaf(w0, a.x, acc[j * 2]); acc[j * 2 + 1] = fmaf(w0, a.y, acc[j * 2 + 1]);
            a = __half22float2(q1[j]);
            acc[j * 2] = fmaf(w1, a.x, acc[j * 2]); acc[j * 2 + 1] = fmaf(w1, a.y, acc[j * 2 + 1]);
            a = __half22float2(q2[j]);
            acc[j * 2] = fmaf(w2, a.x, acc[j * 2]); acc[j * 2 + 1] = fmaf(w2, a.y, acc[j * 2 + 1]);
            a = __half22float2(q3[j]);
            acc[j * 2] = fmaf(w3, a.x, acc[j * 2]); acc[j * 2 + 1] = fmaf(w3, a.y, acc[j * 2 + 1]);
        }
    }
    for (; e < e1; e++) {
        int s0 = g_csr_src[e];
        float w0 = g_dis[s0] * dn;
        uint4 p0 = __ldg((const uint4*)(g_hw + (size_t)s0 * rowlen + f));
        const __half2* q0 = (const __half2*)&p0;
#pragma unroll
        for (int j = 0; j < 4; j++) {
            float2 a = __half22float2(q0[j]);
            acc[j * 2] = fmaf(w0, a.x, acc[j * 2]); acc[j * 2 + 1] = fmaf(w0, a.y, acc[j * 2 + 1]);
        }
    }
    uint4 st;
    __half2* so = (__half2*)&st;
#pragma unroll
    for (int j = 0; j < 4; j++)
        so[j] = __floats2half2_rn(fmaxf(acc[j * 2], 0.f), fmaxf(acc[j * 2 + 1], 0.f));
    *(uint4*)(g_h1 + base + f) = st;
}

// ---------------- layer-2 aggregation (fp8 NC gather) + fc dot + pool + fused final ----
__global__ void __launch_bounds__(256) k_agg2(const float* __restrict__ bias,
                                              const float* __restrict__ fcw,
                                              const float* __restrict__ fcb,
                                              const float* __restrict__ add,
                                              float* __restrict__ out,
                                              int N, int Bsz) {
    int lt = threadIdx.x & 63;
    int node = blockIdx.x * 4 + (threadIdx.x >> 6);
    int f = lt * 8;
    int rowlen = Bsz * HID;
    bool active = (node < N) && (f < rowlen);

    if (active) {
        int h = f & (HID - 1);
        float dn = g_dis[node];
        float sn = dn * dn;
        size_t base = (size_t)node * rowlen;

        float acc[8];
        {
            uint2 sv = __ldg((const uint2*)(g_f8 + base + f));
            float4 a = f8x4_to_f4(sv.x), b = f8x4_to_f4(sv.y);
            acc[0] = fmaf(a.x, sn, bias[h]);     acc[1] = fmaf(a.y, sn, bias[h + 1]);
            acc[2] = fmaf(a.z, sn, bias[h + 2]); acc[3] = fmaf(a.w, sn, bias[h + 3]);
            acc[4] = fmaf(b.x, sn, bias[h + 4]); acc[5] = fmaf(b.y, sn, bias[h + 5]);
            acc[6] = fmaf(b.z, sn, bias[h + 6]); acc[7] = fmaf(b.w, sn, bias[h + 7]);
        }

        int e = g_offs[node], e1 = g_offs[node + 1];
        for (; e + 3 < e1; e += 4) {
            int s0 = g_csr_src[e], s1 = g_csr_src[e + 1];
            int s2 = g_csr_src[e + 2], s3 = g_csr_src[e + 3];
            float w0 = g_dis[s0] * dn, w1 = g_dis[s1] * dn;
            float w2 = g_dis[s2] * dn, w3 = g_dis[s3] * dn;
            uint2 p0 = __ldg((const uint2*)(g_f8 + (size_t)s0 * rowlen + f));
            uint2 p1 = __ldg((const uint2*)(g_f8 + (size_t)s1 * rowlen + f));
            uint2 p2 = __ldg((const uint2*)(g_f8 + (size_t)s2 * rowlen + f));
            uint2 p3 = __ldg((const uint2*)(g_f8 + (size_t)s3 * rowlen + f));
#pragma unroll
            for (int j = 0; j < 2; j++) {
                uint32_t u0 = j ? p0.y : p0.x, u1 = j ? p1.y : p1.x;
                uint32_t u2 = j ? p2.y : p2.x, u3 = j ? p3.y : p3.x;
                float4 m;
                m = f8x4_to_f4(u0);
                acc[j*4+0] = fmaf(w0, m.x, acc[j*4+0]); acc[j*4+1] = fmaf(w0, m.y, acc[j*4+1]);
                acc[j*4+2] = fmaf(w0, m.z, acc[j*4+2]); acc[j*4+3] = fmaf(w0, m.w, acc[j*4+3]);
                m = f8x4_to_f4(u1);
                acc[j*4+0] = fmaf(w1, m.x, acc[j*4+0]); acc[j*4+1] = fmaf(w1, m.y, acc[j*4+1]);
                acc[j*4+2] = fmaf(w1, m.z, acc[j*4+2]); acc[j*4+3] = fmaf(w1, m.w, acc[j*4+3]);
                m = f8x4_to_f4(u2);
                acc[j*4+0] = fmaf(w2, m.x, acc[j*4+0]); acc[j*4+1] = fmaf(w2, m.y, acc[j*4+1]);
                acc[j*4+2] = fmaf(w2, m.z, acc[j*4+2]); acc[j*4+3] = fmaf(w2, m.w, acc[j*4+3]);
                m = f8x4_to_f4(u3);
                acc[j*4+0] = fmaf(w3, m.x, acc[j*4+0]); acc[j*4+1] = fmaf(w3, m.y, acc[j*4+1]);
                acc[j*4+2] = fmaf(w3, m.z, acc[j*4+2]); acc[j*4+3] = fmaf(w3, m.w, acc[j*4+3]);
            }
        }
        for (; e < e1; e++) {
            int s0 = g_csr_src[e];
            float w0 = g_dis[s0] * dn;
            uint2 p0 = __ldg((const uint2*)(g_f8 + (size_t)s0 * rowlen + f));
#pragma unroll
            for (int j = 0; j < 2; j++) {
                float4 m = f8x4_to_f4(j ? p0.y : p0.x);
                acc[j*4+0] = fmaf(w0, m.x, acc[j*4+0]); acc[j*4+1] = fmaf(w0, m.y, acc[j*4+1]);
                acc[j*4+2] = fmaf(w0, m.z, acc[j*4+2]); acc[j*4+3] = fmaf(w0, m.w, acc[j*4+3]);
            }
        }

        int h0 = f & (HID - 1);
        float c = 0.f;
#pragma unroll
        for (int j = 0; j < 8; j++) c = fmaf(fmaxf(acc[j], 0.f), fcw[h0 + j], c);
#pragma unroll
        for (int o = 4; o; o >>= 1) c += __shfl_xor_sync(0xffffffffu, c, o);
        if ((threadIdx.x & 7) == 0) {
            int b = lt >> 3;
            atomicAdd(&g_partial[b * 64 + (node & 63)], c);
        }
    }

    // -------- tail-block fused final reduce --------
    __shared__ bool isLast;
    if (threadIdx.x == 0) {
        __threadfence();
        unsigned int t = atomicAdd(&g_done, 1u);
        isLast = (t == gridDim.x - 1);
    }
    __syncthreads();
    if (isLast) {
        __threadfence();
        int b = threadIdx.x >> 5;
        int lane = threadIdx.x & 31;
        float s = 0.f;
        if (b < Bsz)
            s = g_partial[b * 64 + lane] + g_partial[b * 64 + 32 + lane];
#pragma unroll
        for (int o = 16; o; o >>= 1) s += __shfl_xor_sync(0xffffffffu, s, o);
        if (b < Bsz && lane == 0)
            out[b] = s * (1.0f / (float)N) + add[b] * fcw[HID] + fcb[0];
        __syncthreads();
        for (int i = threadIdx.x; i < MAXB * 64; i += 256) g_partial[i] = 0.f;
        if (threadIdx.x == 0) g_done = 0u;
    }
}

// ---------------- launch ----------------
extern "C" void kernel_launch(void* const* d_in, const int* in_sizes, int n_in,
                              void* d_out, int out_size) {
    const float* x   = (const float*)d_in[0];
    const float* add = (const float*)d_in[1];
    const int*   ei  = (const int*)d_in[2];
    const float* W1  = (const float*)d_in[3];
    const float* b1  = (const float*)d_in[4];
    const float* W2  = (const float*)d_in[5];
    const float* b2  = (const float*)d_in[6];
    const float* fcw = (const float*)d_in[7];
    const float* fcb = (const float*)d_in[8];
    float* out = (float*)d_out;

    int B = in_sizes[1];
    int E = in_sizes[2] / 2;
    int N = in_sizes[0] / (B * FIN);
    int rows = B * N;

    static cudaStream_t s_side = nullptr;
    static cudaEvent_t ev_fork = nullptr, ev_join = nullptr;
    if (s_side == nullptr) {
        cudaStreamCreateWithFlags(&s_side, cudaStreamNonBlocking);
        cudaEventCreateWithFlags(&ev_fork, cudaEventDisableTiming);
        cudaEventCreateWithFlags(&ev_join, cudaEventDisableTiming);
    }

    // fork: graph structure (needs only edge_index) beside wconv+gemm1
    cudaEventRecord(ev_fork, 0);
    cudaStreamWaitEvent(s_side, ev_fork, 0);
    k_count<<<(E / 4 + 256) / 256, 256, 0, s_side>>>(ei, E);
    k_scan<<<1, 1024, 0, s_side>>>(N);
    k_csr<<<(E + 255) / 256, 256, 0, s_side>>>(ei, E);
    cudaEventRecord(ev_join, s_side);

    k_wconv<<<(FIN * HID + HID * HID + 255) / 256, 256>>>(W1, W2);
    k_gemm1<<<(rows + 63) / 64, 128>>>(x, rows, N, B);

    // join: agg1 needs both csr and gemm1 output
    cudaStreamWaitEvent(0, ev_join, 0);
    k_agg1<<<(N + 3) / 4, 256>>>(b1, N, B);
    k_gemm2<<<(rows + 63) / 64, 128>>>(rows);
    k_agg2<<<(N + 3) / 4, 256>>>(b2, fcw, fcb, add, out, N, B);
}